// round 13
// baseline (speedup 1.0000x reference)
#include <cuda_runtime.h>
#include <math.h>

#define BB 2
#define TT 512
#define DD 64
#define LAYERS 4
#define HH 32
#define NTOK (BB*TT)
#define FDIM 128            // u (64) + v (64)
#define EPSF 1e-8f
#define C2F 7.0710678e-5f   // sqrt(EPS/2)

// dynamic smem layout for k_attn
#define OFF_LEPR   0
#define OFF_WFA    8192
#define OFF_WFB    16384
#define OFF_RF2S   24576
#define OFF_SWG    26624      // 64 rows x 144 floats (pad 144 => conflict-free)
#define OFF_SO     63488
#define OFF_SPREV  64512
#define OFF_SU     65536
#define OFF_SV     66816
#define OFF_WSUM   68096
#define OFF_SRED   68352
#define SMEM_ATTN  69632

typedef unsigned long long u64;
typedef unsigned int u32;

__device__ float g_bufA[NTOK*DD];
__device__ float g_bufB[NTOK*DD];
__device__ float g_prev[LAYERS][NTOK*DD];
__device__ float2 g_featP[(FDIM/2)*NTOK];   // [dimpair][token] packed
__device__ float g_basin[DD];
__device__ float g_temps[LAYERS];
__device__ float g_res[LAYERS];
__device__ float g_poolacc[BB*DD];

__device__ __forceinline__ u64 pack2(float x, float y) {
    u64 r;
    asm("mov.b64 %0, {%1, %2};" : "=l"(r) : "r"(__float_as_uint(x)), "r"(__float_as_uint(y)));
    return r;
}
__device__ __forceinline__ u64 bcast2(float x) { return pack2(x, x); }
__device__ __forceinline__ void fma2(u64& d, u64 a, u64 b) {
    asm("fma.rn.f32x2 %0, %1, %2, %0;" : "+l"(d) : "l"(a), "l"(b));
}
__device__ __forceinline__ void unpack2(u64 v, float& lo, float& hi) {
    u32 a, b;
    asm("mov.b64 {%0, %1}, %2;" : "=r"(a), "=r"(b) : "l"(v));
    lo = __uint_as_float(a); hi = __uint_as_float(b);
}

// acos for x in [-1,1], |err| ~2e-8 (A&S 4.4.45)
__device__ __forceinline__ float acos_fast(float x) {
    float ax = fabsf(x);
    float r = sqrtf(1.0f - ax);
    float p = fmaf(ax, -0.0012624911f, 0.0066700901f);
    p = fmaf(ax, p, -0.0170881256f);
    p = fmaf(ax, p, 0.0308918810f);
    p = fmaf(ax, p, -0.0501743046f);
    p = fmaf(ax, p, 0.0889789874f);
    p = fmaf(ax, p, -0.2145988016f);
    p = fmaf(ax, p, 1.5707963050f);
    float res = r * p;
    return (x < 0.f) ? (3.14159265358979f - res) : res;
}

// ---------------------------------------------------------------------------
// feat0: copy src -> bufA, init basin/temps/res/poolacc, build packed
// features for pass0/layer0. 16 tokens/block, warp = token, grid 64.
__global__ void __launch_bounds__(512) k_feat0(
        const float* __restrict__ src,
        const float* __restrict__ basin_coords,
        const float* __restrict__ W_temp,
        const float* __restrict__ b_temp,
        const float* __restrict__ res_scale) {
    int tid = threadIdx.x;
    int wid = tid >> 5, c = tid & 31;
    int tok0 = blockIdx.x * 16;
    int tok = tok0 + wid;

    __shared__ float sfeat[FDIM][17];

    if (blockIdx.x == 0) {
        if (wid == 0) {
            g_basin[c]      = basin_coords[c];
            g_basin[c + 32] = basin_coords[c + 32];
            if (c < LAYERS) {
                g_res[c] = res_scale[c];
                float acc = b_temp[c];
                #pragma unroll 8
                for (int d2 = 0; d2 < DD; ++d2)
                    acc = fmaf(W_temp[c*DD + d2], basin_coords[d2], acc);
                g_temps[c] = 1.f/(1.f + expf(-acc)) + 0.5f;
            }
        }
        if (tid >= 128 && tid < 256) g_poolacc[tid - 128] = 0.f;
    }

    float xn0 = src[tok*64 + c];
    float xn1 = src[tok*64 + c + 32];
    g_bufA[tok*64 + c]      = xn0;
    g_bufA[tok*64 + c + 32] = xn1;

    float sp0 = fmaxf(xn0, 0.f) + log1pf(__expf(-fabsf(xn0)));
    float sp1 = fmaxf(xn1, 0.f) + log1pf(__expf(-fabsf(xn1)));

    float v = sp0 + sp1;
    #pragma unroll
    for (int o = 16; o; o >>= 1) v += __shfl_xor_sync(0xffffffffu, v, o);
    float s1 = v + EPSF;
    float q0 = fmaxf(sp0/s1, EPSF), q1 = fmaxf(sp1/s1, EPSF);
    v = q0 + q1;
    #pragma unroll
    for (int o = 16; o; o >>= 1) v += __shfl_xor_sync(0xffffffffu, v, o);
    float s2 = v + EPSF;
    float p0 = q0/s2, p1 = q1/s2;

    float u0 = sqrtf(p0), u1 = sqrtf(p1);
    sfeat[c][wid]       = u0;
    sfeat[c+32][wid]    = u1;
    sfeat[64+c][wid]    = C2F/u0;
    sfeat[96+c][wid]    = C2F/u1;
    __syncthreads();

    // packed transposed store: dim-pair major, 16 tokens contiguous
    #pragma unroll
    for (int i = tid; i < (FDIM/2)*16; i += 512) {
        int dp = i >> 4, t = i & 15;
        g_featP[dp*NTOK + tok0 + t] = make_float2(sfeat[2*dp][t], sfeat[2*dp+1][t]);
    }
}

// ---------------------------------------------------------------------------
// attention + fused next-layer feature build (+ fused pool partials).
// 4 rows/block, grid 256, 512 threads, 2 blocks/SM (dynamic smem 68.6KB).
// W_fb for the next layer's gate is staged into smem at kernel START so its
// global-load latency hides behind phase 1 instead of stalling the epilogue.
__global__ void __launch_bounds__(512, 2)
k_attn(int cursel, int l, int snap, int fin, int doFeat, int nextGated, int nextL,
       int doPool,
       const float* __restrict__ W_fb, const float* __restrict__ b_fb,
       const float* __restrict__ seq, const float* __restrict__ resg,
       float* __restrict__ out) {
    const float* xin = cursel ? g_bufB : g_bufA;
    float*       xout = cursel ? g_bufA : g_bufB;

    int blk = blockIdx.x;
    int b = blk >> 7;
    int rowBase = (blk & 127) << 2;
    int tid = threadIdx.x, w = tid >> 5, c = tid & 31;

    extern __shared__ __align__(16) char dsm[];
    u64 (*LePr)[2]     = (u64(*)[2])(dsm + OFF_LEPR);      // [TT][rowpair]
    u64 (*wFA)[2][32]  = (u64(*)[2][32])(dsm + OFF_WFA);
    u64 (*wFB)[2][32]  = (u64(*)[2][32])(dsm + OFF_WFB);
    u64 (*rf2s)[2]     = (u64(*)[2])(dsm + OFF_RF2S);      // [dim][rowpair]
    float* sWg         = (float*)(dsm + OFF_SWG);          // [64][144]
    float (*so)[64]    = (float(*)[64])(dsm + OFF_SO);
    float (*sprev)[64] = (float(*)[64])(dsm + OFF_SPREV);
    float (*su)[5]     = (float(*)[5])(dsm + OFF_SU);
    float (*sv)[5]     = (float(*)[5])(dsm + OFF_SV);
    float (*wSum)[4]   = (float(*)[4])(dsm + OFF_WSUM);
    float (*sred)[4]   = (float(*)[4])(dsm + OFF_SRED);

    float nInvT = -1.f / fmaxf(g_temps[l], 1e-6f);

    // early W staging for the gated epilogue (latency hidden by phase 1)
    if (doFeat && nextGated) {
        const float* Wg = W_fb + nextL*DD*2*DD;
        #pragma unroll
        for (int i = tid; i < 64*128; i += 512)
            sWg[(i>>7)*144 + (i&127)] = Wg[i];
    }

    // stage row features: thread = (dim dd, rowpair rp)
    if (tid < 256) {
        int dd = tid >> 1, rp = tid & 1;
        const float* gfp = (const float*)g_featP;
        int base = (dd >> 1)*(2*NTOK) + (dd & 1);
        int t0 = b*TT + rowBase + 2*rp;
        float f0 = gfp[base + 2*t0];
        float f1 = gfp[base + 2*(t0+1)];
        rf2s[dd][rp] = pack2(f0, f1);
    }
    __syncthreads();

    // phase 1: 128-dot for this lane's j, 4 rows via 2 packed accumulators
    // (4-in-flight float2 prefetch — measured-best configuration)
    int jl = w*32 + c;
    const float2* fp = g_featP + b*TT + jl;
    u64 acc0 = 0ull, acc1 = 0ull;
    float2 jv[4], jvn[4];
    #pragma unroll
    for (int q = 0; q < 4; ++q) { jv[q] = fp[q*NTOK]; jvn[q] = make_float2(0.f, 0.f); }
    #pragma unroll 1
    for (int dp0 = 0; dp0 < FDIM/2; dp0 += 4) {
        if (dp0 + 4 < FDIM/2) {
            #pragma unroll
            for (int q = 0; q < 4; ++q) jvn[q] = fp[(dp0+4+q)*NTOK];
        }
        #pragma unroll
        for (int q = 0; q < 4; ++q) {
            int dp = dp0 + q;
            const ulonglong2 rA = *(const ulonglong2*)&rf2s[2*dp][0];
            const ulonglong2 rB = *(const ulonglong2*)&rf2s[2*dp+1][0];
            u64 jx = bcast2(jv[q].x);
            u64 jy = bcast2(jv[q].y);
            fma2(acc0, rA.x, jx);
            fma2(acc1, rA.y, jx);
            fma2(acc0, rB.x, jy);
            fma2(acc1, rB.y, jy);
        }
        #pragma unroll
        for (int q = 0; q < 4; ++q) jv[q] = jvn[q];
    }

    // e = exp(2*acos(clip)*nInvT) (no-max softmax: logits in [-12.6, 0])
    float i0, i1, i2, i3;
    unpack2(acc0, i0, i1);
    unpack2(acc1, i2, i3);
    i0 = fminf(fmaxf(i0, -1.f + 1e-6f), 1.f - 1e-6f);
    i1 = fminf(fmaxf(i1, -1.f + 1e-6f), 1.f - 1e-6f);
    i2 = fminf(fmaxf(i2, -1.f + 1e-6f), 1.f - 1e-6f);
    i3 = fminf(fmaxf(i3, -1.f + 1e-6f), 1.f - 1e-6f);
    float e0 = __expf(2.f*acos_fast(i0)*nInvT);
    float e1 = __expf(2.f*acos_fast(i1)*nInvT);
    float e2 = __expf(2.f*acos_fast(i2)*nInvT);
    float e3 = __expf(2.f*acos_fast(i3)*nInvT);
    {
        ulonglong2 ev;
        ev.x = pack2(e0, e1);
        ev.y = pack2(e2, e3);
        *(ulonglong2*)&LePr[jl][0] = ev;
    }
    float es[4] = {e0, e1, e2, e3};
    #pragma unroll
    for (int r = 0; r < 4; ++r) {
        float sv2 = es[r];
        #pragma unroll
        for (int o = 16; o; o >>= 1) sv2 += __shfl_xor_sync(0xffffffffu, sv2, o);
        if (c == 0) wSum[w][r] = sv2;
    }
    __syncthreads();

    // phase 3: value accumulation, 16 warps x 32 j, 1-ahead prefetch
    {
        u64 fA0 = 0ull, fA1 = 0ull, fB0 = 0ull, fB1 = 0ull;
        const float2* xb2 = (const float2*)(xin + b*TT*DD);
        int j0 = w*32;
        float2 xv = xb2[j0*32 + c];
        #pragma unroll 4
        for (int jj = 0; jj < 32; ++jj) {
            int j = j0 + jj;
            float2 nx = make_float2(0.f, 0.f);
            if (jj < 31) nx = xb2[(j+1)*32 + c];
            ulonglong2 ep = *(const ulonglong2*)&LePr[j][0];
            u64 xA = bcast2(xv.x), xB = bcast2(xv.y);
            fma2(fA0, ep.x, xA);
            fma2(fA1, ep.y, xA);
            fma2(fB0, ep.x, xB);
            fma2(fB1, ep.y, xB);
            xv = nx;
        }
        wFA[w][0][c] = fA0; wFA[w][1][c] = fA1;
        wFB[w][0][c] = fB0; wFB[w][1][c] = fB1;
    }
    __syncthreads();

    // merge: thread = (row r, dim d), 256 threads
    int r = tid >> 6, d = tid & 63;
    int rr = r & 3;
    if (tid < 256) {
        int q = r >> 1, sel = r & 1;
        int cc = d >> 1, ab = d & 1;
        float F = 0.f, S = 0.f;
        #pragma unroll
        for (int ww = 0; ww < 16; ++ww) {
            u64 fp2 = ab ? wFB[ww][q][cc] : wFA[ww][q][cc];
            float lo, hi;
            unpack2(fp2, lo, hi);
            F += sel ? hi : lo;
            S += wSum[ww][r];
        }
        int tok = b*TT + rowBase + r;
        float rs = g_res[l];
        float xv = xin[tok*DD + d];
        float o = xv + rs*(F/S - xv);
        so[r][d] = o;
        if (snap) g_prev[l][tok*DD + d] = o;
        if (!(doFeat && nextGated)) xout[tok*DD + d] = o;
        if (fin)  out[tok*DD + d] = o + 0.01f*resg[0]*(o - seq[tok*DD + d]);
        if (doFeat && nextGated) sprev[r][d] = g_prev[nextL][tok*DD + d];
    }
    if (!doFeat) return;
    __syncthreads();

    // fused pool partials (only on p0/l3 launch): sum the block's 4 rows
    if (doPool && tid < 64) {
        float ps = so[0][tid] + so[1][tid] + so[2][tid] + so[3][tid];
        atomicAdd(&g_poolacc[b*DD + tid], ps);
    }

    // ------- fused next-layer feature build (W already staged) -------
    float xfeat = 0.f;
    if (nextGated) {
        if (tid < 256) {
            float acc = b_fb[nextL*DD + d];
            const float4* Wr = (const float4*)&sWg[d*144];
            const float4* xr4 = (const float4*)&so[rr][0];
            const float4* pr4 = (const float4*)&sprev[rr][0];
            #pragma unroll
            for (int q2 = 0; q2 < 16; ++q2) {
                float4 wv = Wr[q2], vv = xr4[q2];
                acc += wv.x*vv.x + wv.y*vv.y + wv.z*vv.z + wv.w*vv.w;
            }
            #pragma unroll
            for (int q2 = 0; q2 < 16; ++q2) {
                float4 wv = Wr[16+q2], vv = pr4[q2];
                acc += wv.x*vv.x + wv.y*vv.y + wv.z*vv.z + wv.w*vv.w;
            }
            float g = 1.f/(1.f + __expf(-acc));
            xfeat = so[rr][d]*g + sprev[rr][d]*(1.f - g);
            int tok = b*TT + rowBase + rr;
            xout[tok*DD + d] = xfeat;
        }
    } else {
        xfeat = so[rr][d];
    }

    // simplex projection per token (dims of token rr live in 2 warps)
    float sp = fmaxf(xfeat, 0.f) + log1pf(__expf(-fabsf(xfeat)));
    int half = (d >> 5) & 1;
    float v1 = sp;
    #pragma unroll
    for (int o = 16; o; o >>= 1) v1 += __shfl_xor_sync(0xffffffffu, v1, o);
    if (tid < 256 && (tid & 31) == 0) sred[r][half] = v1;
    __syncthreads();
    float s1 = sred[rr][0] + sred[rr][1] + EPSF;
    float sfrac = fmaxf(sp/s1, EPSF);
    float v2 = sfrac;
    #pragma unroll
    for (int o = 16; o; o >>= 1) v2 += __shfl_xor_sync(0xffffffffu, v2, o);
    if (tid < 256 && (tid & 31) == 0) sred[r][2 + half] = v2;
    __syncthreads();
    float s2 = sred[rr][2] + sred[rr][3] + EPSF;
    float pfin = sfrac/s2;

    if (tid < 256) {
        float u = sqrtf(pfin);
        su[d][r] = u;
        sv[d][r] = C2F/u;
    }
    __syncthreads();

    // write packed features for the block's 4 tokens
    if (tid < 256) {
        int dp = tid >> 2, tk = tid & 3;
        int d0 = 2*dp, d1 = 2*dp + 1;
        float f0 = (d0 < 64) ? su[d0][tk] : sv[d0-64][tk];
        float f1 = (d1 < 64) ? su[d1][tk] : sv[d1-64][tk];
        g_featP[dp*NTOK + b*TT + rowBase + tk] = make_float2(f0, f1);
    }
}

// ---------------------------------------------------------------------------
// pool MLP only — pooled sums come from fused atomics in k_attn(p0,l3).
__global__ void __launch_bounds__(128) k_pool(
                       const float* __restrict__ Wc1, const float* __restrict__ bc1,
                       const float* __restrict__ Wc2, const float* __restrict__ bc2,
                       const float* __restrict__ Wu,  const float* __restrict__ bu,
                       const float* __restrict__ W_temp, const float* __restrict__ b_temp) {
    int tid = threadIdx.x;
    __shared__ float pooled[BB][DD];
    __shared__ float h1[BB][HH];
    __shared__ float hb[BB][DD];
    __shared__ float agg[DD], comb[2*DD], nb[DD];

    pooled[tid>>6][tid&63] = g_poolacc[tid] * (1.f/TT);
    __syncthreads();
    if (tid < BB*HH) {
        int bb = tid / HH, h = tid - bb*HH;
        float a = bc1[h];
        #pragma unroll 8
        for (int k = 0; k < DD; ++k) a = fmaf(pooled[bb][k], Wc1[h*DD + k], a);
        h1[bb][h] = tanhf(a);
    }
    __syncthreads();
    {
        int b = tid >> 6, d = tid & 63;
        float a = bc2[d];
        #pragma unroll 8
        for (int k = 0; k < HH; ++k) a = fmaf(h1[b][k], Wc2[d*HH + k], a);
        hb[b][d] = tanhf(a);
    }
    __syncthreads();
    if (tid < DD) {
        float a = 0.5f*(hb[0][tid] + hb[1][tid]);
        agg[tid]      = a;
        comb[tid]     = g_basin[tid];
        comb[DD+tid]  = a;
    }
    __syncthreads();
    if (tid < DD) {
        float a = bu[tid];
        #pragma unroll 8
        for (int k = 0; k < 2*DD; ++k) a = fmaf(Wu[tid*2*DD + k], comb[k], a);
        float g = 1.f/(1.f + expf(-a));
        nb[tid] = g_basin[tid]*(1.f - g) + agg[tid]*g;
        g_basin[tid] = nb[tid];
    }
    __syncthreads();
    if (tid < LAYERS) {
        float acc = b_temp[tid];
        #pragma unroll 8
        for (int k = 0; k < DD; ++k) acc = fmaf(W_temp[tid*DD + k], nb[k], acc);
        g_temps[tid] = 1.f/(1.f + expf(-acc)) + 0.5f;
    }
}

// ---------------------------------------------------------------------------
extern "C" void kernel_launch(void* const* d_in, const int* in_sizes, int n_in,
                              void* d_out, int out_size) {
    const float* basin_seq    = (const float*)d_in[0];
    const float* basin_coords = (const float*)d_in[1];
    const float* W_temp       = (const float*)d_in[2];
    const float* b_temp       = (const float*)d_in[3];
    const float* res_scale    = (const float*)d_in[4];
    const float* W_fb         = (const float*)d_in[5];
    const float* b_fb         = (const float*)d_in[6];
    const float* Wc1          = (const float*)d_in[7];
    const float* bc1          = (const float*)d_in[8];
    const float* Wc2          = (const float*)d_in[9];
    const float* bc2          = (const float*)d_in[10];
    const float* Wu           = (const float*)d_in[11];
    const float* bu           = (const float*)d_in[12];
    const float* res_g        = (const float*)d_in[13];

    cudaFuncSetAttribute(k_attn, cudaFuncAttributeMaxDynamicSharedMemorySize,
                         SMEM_ATTN);

    k_feat0<<<NTOK/16, 512>>>(basin_seq, basin_coords, W_temp, b_temp, res_scale);

    int cursel = 0;
    for (int p = 0; p < 2; ++p) {
        for (int l = 0; l < LAYERS; ++l) {
            int last = (p == 1 && l == LAYERS-1);
            int doFeat = !last;
            int nextGated = (p == 1) || (l == LAYERS-1);
            int nextL = (l + 1) & 3;
            int doPool = (p == 0 && l == LAYERS-1) ? 1 : 0;
            k_attn<<<NTOK/4, 512, SMEM_ATTN>>>(cursel, l, p == 0 ? 1 : 0, last,
                                    doFeat, nextGated, nextL, doPool, W_fb, b_fb,
                                    basin_seq, res_g, (float*)d_out);
            cursel ^= 1;
            if (p == 0 && l == LAYERS-1) {
                k_pool<<<1, 128>>>(Wc1, bc1, Wc2, bc2, Wu, bu, W_temp, b_temp);
            }
        }
    }
}

// round 15
// speedup vs baseline: 1.0567x; 1.0567x over previous
#include <cuda_runtime.h>
#include <math.h>

#define BB 2
#define TT 512
#define DD 64
#define LAYERS 4
#define HH 32
#define NTOK (BB*TT)
#define FDIM 128            // u (64) + v (64)
#define EPSF 1e-8f
#define C2F 7.0710678e-5f   // sqrt(EPS/2)

typedef unsigned long long u64;
typedef unsigned int u32;

__device__ float g_bufA[NTOK*DD];
__device__ float g_bufB[NTOK*DD];
__device__ float g_prev[LAYERS][NTOK*DD];
__device__ float2 g_featP[(FDIM/2)*NTOK];   // [dimpair][token] packed
__device__ float g_basin[DD];
__device__ float g_temps[LAYERS];
__device__ float g_res[LAYERS];
__device__ float g_poolacc[BB*DD];
__device__ int   g_cnt;

__device__ __forceinline__ u64 pack2(float x, float y) {
    u64 r;
    asm("mov.b64 %0, {%1, %2};" : "=l"(r) : "r"(__float_as_uint(x)), "r"(__float_as_uint(y)));
    return r;
}
__device__ __forceinline__ u64 bcast2(float x) { return pack2(x, x); }
__device__ __forceinline__ void fma2(u64& d, u64 a, u64 b) {
    asm("fma.rn.f32x2 %0, %1, %2, %0;" : "+l"(d) : "l"(a), "l"(b));
}
__device__ __forceinline__ void unpack2(u64 v, float& lo, float& hi) {
    u32 a, b;
    asm("mov.b64 {%0, %1}, %2;" : "=r"(a), "=r"(b) : "l"(v));
    lo = __uint_as_float(a); hi = __uint_as_float(b);
}

// acos for x in [-1,1], |err| ~2e-8 (A&S 4.4.45)
__device__ __forceinline__ float acos_fast(float x) {
    float ax = fabsf(x);
    float r = sqrtf(1.0f - ax);
    float p = fmaf(ax, -0.0012624911f, 0.0066700901f);
    p = fmaf(ax, p, -0.0170881256f);
    p = fmaf(ax, p, 0.0308918810f);
    p = fmaf(ax, p, -0.0501743046f);
    p = fmaf(ax, p, 0.0889789874f);
    p = fmaf(ax, p, -0.2145988016f);
    p = fmaf(ax, p, 1.5707963050f);
    float res = r * p;
    return (x < 0.f) ? (3.14159265358979f - res) : res;
}

// ---------------------------------------------------------------------------
// feat0: copy src -> bufA, init basin/temps/res/poolacc/cnt, build packed
// features for pass0/layer0. 16 tokens/block, warp = token, grid 64.
__global__ void __launch_bounds__(512) k_feat0(
        const float* __restrict__ src,
        const float* __restrict__ basin_coords,
        const float* __restrict__ W_temp,
        const float* __restrict__ b_temp,
        const float* __restrict__ res_scale) {
    int tid = threadIdx.x;
    int wid = tid >> 5, c = tid & 31;
    int tok0 = blockIdx.x * 16;
    int tok = tok0 + wid;

    __shared__ float sfeat[FDIM][17];

    if (blockIdx.x == 0) {
        if (wid == 0) {
            g_basin[c]      = basin_coords[c];
            g_basin[c + 32] = basin_coords[c + 32];
            if (c == 0) g_cnt = 0;
            if (c < LAYERS) {
                g_res[c] = res_scale[c];
                float acc = b_temp[c];
                #pragma unroll 8
                for (int d2 = 0; d2 < DD; ++d2)
                    acc = fmaf(W_temp[c*DD + d2], basin_coords[d2], acc);
                g_temps[c] = 1.f/(1.f + expf(-acc)) + 0.5f;
            }
        }
        if (tid >= 128 && tid < 256) g_poolacc[tid - 128] = 0.f;
    }

    float xn0 = src[tok*64 + c];
    float xn1 = src[tok*64 + c + 32];
    g_bufA[tok*64 + c]      = xn0;
    g_bufA[tok*64 + c + 32] = xn1;

    float sp0 = fmaxf(xn0, 0.f) + log1pf(__expf(-fabsf(xn0)));
    float sp1 = fmaxf(xn1, 0.f) + log1pf(__expf(-fabsf(xn1)));

    float v = sp0 + sp1;
    #pragma unroll
    for (int o = 16; o; o >>= 1) v += __shfl_xor_sync(0xffffffffu, v, o);
    float s1 = v + EPSF;
    float q0 = fmaxf(sp0/s1, EPSF), q1 = fmaxf(sp1/s1, EPSF);
    v = q0 + q1;
    #pragma unroll
    for (int o = 16; o; o >>= 1) v += __shfl_xor_sync(0xffffffffu, v, o);
    float s2 = v + EPSF;
    float p0 = q0/s2, p1 = q1/s2;

    float u0 = sqrtf(p0), u1 = sqrtf(p1);
    sfeat[c][wid]       = u0;
    sfeat[c+32][wid]    = u1;
    sfeat[64+c][wid]    = C2F/u0;
    sfeat[96+c][wid]    = C2F/u1;
    __syncthreads();

    // packed transposed store: dim-pair major, 16 tokens contiguous
    #pragma unroll
    for (int i = tid; i < (FDIM/2)*16; i += 512) {
        int dp = i >> 4, t = i & 15;
        g_featP[dp*NTOK + tok0 + t] = make_float2(sfeat[2*dp][t], sfeat[2*dp+1][t]);
    }
}

// ---------------------------------------------------------------------------
// attention + fused next-layer feature build (+ fused pool partials, and on
// the doPool launch the LAST block runs the compress-MLP/basin/temps update).
// 4 rows/block, grid 256, 512 threads, 2 blocks/SM.
__global__ void __launch_bounds__(512, 2)
k_attn(int cursel, int l, int snap, int fin, int doFeat, int nextGated, int nextL,
       int doPool,
       const float* __restrict__ W_fb, const float* __restrict__ b_fb,
       const float* __restrict__ seq, const float* __restrict__ resg,
       float* __restrict__ out,
       const float* __restrict__ Wc1, const float* __restrict__ bc1,
       const float* __restrict__ Wc2, const float* __restrict__ bc2,
       const float* __restrict__ Wu,  const float* __restrict__ bu,
       const float* __restrict__ W_temp, const float* __restrict__ b_temp) {
    const float* xin = cursel ? g_bufB : g_bufA;
    float*       xout = cursel ? g_bufA : g_bufB;

    int blk = blockIdx.x;
    int b = blk >> 7;
    int rowBase = (blk & 127) << 2;
    int tid = threadIdx.x, w = tid >> 5, c = tid & 31;

    // blob: LePr (8K) | wFA (8K) | wFB (8K). sWh (GEMV stage, 19456B) aliases
    // LePr+wFA+start of wFB, all dead by the time the epilogue GEMV runs.
    __shared__ __align__(16) char smemBlob[24576];
    u64 (*LePr)[2]     = (u64(*)[2])(smemBlob);            // [TT][rowpair]
    u64 (*wFA)[2][32]  = (u64(*)[2][32])(smemBlob + 8192);
    u64 (*wFB)[2][32]  = (u64(*)[2][32])(smemBlob + 16384);
    float* sWh         = (float*)smemBlob;                 // [64][76]

    __shared__ __align__(16) u64 rf2s[FDIM][2];   // [dim][rowpair] packed rows
    __shared__ float so[4][64], sprev[4][64];
    __shared__ float su[64][5], sv[64][5];
    __shared__ float wSum[16][4];
    __shared__ float sred[4][4];
    __shared__ int sIsLast;

    float nInvT = -1.f / fmaxf(g_temps[l], 1e-6f);

    // stage row features: thread = (dim dd, rowpair rp)
    if (tid < 256) {
        int dd = tid >> 1, rp = tid & 1;
        const float* gfp = (const float*)g_featP;
        int base = (dd >> 1)*(2*NTOK) + (dd & 1);
        int t0 = b*TT + rowBase + 2*rp;
        float f0 = gfp[base + 2*t0];
        float f1 = gfp[base + 2*(t0+1)];
        rf2s[dd][rp] = pack2(f0, f1);
    }
    __syncthreads();

    // phase 1: 128-dot for this lane's j, 4 rows via 2 packed accumulators
    // (4-in-flight float2 prefetch — measured-best configuration)
    int jl = w*32 + c;
    const float2* fp = g_featP + b*TT + jl;
    u64 acc0 = 0ull, acc1 = 0ull;
    float2 jv[4], jvn[4];
    #pragma unroll
    for (int q = 0; q < 4; ++q) { jv[q] = fp[q*NTOK]; jvn[q] = make_float2(0.f, 0.f); }
    #pragma unroll 1
    for (int dp0 = 0; dp0 < FDIM/2; dp0 += 4) {
        if (dp0 + 4 < FDIM/2) {
            #pragma unroll
            for (int q = 0; q < 4; ++q) jvn[q] = fp[(dp0+4+q)*NTOK];
        }
        #pragma unroll
        for (int q = 0; q < 4; ++q) {
            int dp = dp0 + q;
            const ulonglong2 rA = *(const ulonglong2*)&rf2s[2*dp][0];
            const ulonglong2 rB = *(const ulonglong2*)&rf2s[2*dp+1][0];
            u64 jx = bcast2(jv[q].x);
            u64 jy = bcast2(jv[q].y);
            fma2(acc0, rA.x, jx);
            fma2(acc1, rA.y, jx);
            fma2(acc0, rB.x, jy);
            fma2(acc1, rB.y, jy);
        }
        #pragma unroll
        for (int q = 0; q < 4; ++q) jv[q] = jvn[q];
    }

    // e = exp(2*acos(clip)*nInvT) (no-max softmax: logits in [-12.6, 0])
    float i0, i1, i2, i3;
    unpack2(acc0, i0, i1);
    unpack2(acc1, i2, i3);
    i0 = fminf(fmaxf(i0, -1.f + 1e-6f), 1.f - 1e-6f);
    i1 = fminf(fmaxf(i1, -1.f + 1e-6f), 1.f - 1e-6f);
    i2 = fminf(fmaxf(i2, -1.f + 1e-6f), 1.f - 1e-6f);
    i3 = fminf(fmaxf(i3, -1.f + 1e-6f), 1.f - 1e-6f);
    float e0 = __expf(2.f*acos_fast(i0)*nInvT);
    float e1 = __expf(2.f*acos_fast(i1)*nInvT);
    float e2 = __expf(2.f*acos_fast(i2)*nInvT);
    float e3 = __expf(2.f*acos_fast(i3)*nInvT);
    {
        ulonglong2 ev;
        ev.x = pack2(e0, e1);
        ev.y = pack2(e2, e3);
        *(ulonglong2*)&LePr[jl][0] = ev;
    }
    float es[4] = {e0, e1, e2, e3};
    #pragma unroll
    for (int r = 0; r < 4; ++r) {
        float sv2 = es[r];
        #pragma unroll
        for (int o = 16; o; o >>= 1) sv2 += __shfl_xor_sync(0xffffffffu, sv2, o);
        if (c == 0) wSum[w][r] = sv2;
    }
    __syncthreads();

    // phase 3: value accumulation, 16 warps x 32 j, 1-ahead prefetch
    {
        u64 fA0 = 0ull, fA1 = 0ull, fB0 = 0ull, fB1 = 0ull;
        const float2* xb2 = (const float2*)(xin + b*TT*DD);
        int j0 = w*32;
        float2 xv = xb2[j0*32 + c];
        #pragma unroll 4
        for (int jj = 0; jj < 32; ++jj) {
            int j = j0 + jj;
            float2 nx = make_float2(0.f, 0.f);
            if (jj < 31) nx = xb2[(j+1)*32 + c];
            ulonglong2 ep = *(const ulonglong2*)&LePr[j][0];
            u64 xA = bcast2(xv.x), xB = bcast2(xv.y);
            fma2(fA0, ep.x, xA);
            fma2(fA1, ep.y, xA);
            fma2(fB0, ep.x, xB);
            fma2(fB1, ep.y, xB);
            xv = nx;
        }
        wFA[w][0][c] = fA0; wFA[w][1][c] = fA1;
        wFB[w][0][c] = fB0; wFB[w][1][c] = fB1;
    }
    __syncthreads();

    // merge: thread = (row r, dim d), 256 threads
    int r = tid >> 6, d = tid & 63;
    int rr = r & 3;
    if (tid < 256) {
        int q = r >> 1, sel = r & 1;
        int cc = d >> 1, ab = d & 1;
        float F = 0.f, S = 0.f;
        #pragma unroll
        for (int ww = 0; ww < 16; ++ww) {
            u64 fp2 = ab ? wFB[ww][q][cc] : wFA[ww][q][cc];
            float lo, hi;
            unpack2(fp2, lo, hi);
            F += sel ? hi : lo;
            S += wSum[ww][r];
        }
        int tok = b*TT + rowBase + r;
        float rs = g_res[l];
        float xv = xin[tok*DD + d];
        float o = xv + rs*(F/S - xv);
        so[r][d] = o;
        if (snap) g_prev[l][tok*DD + d] = o;
        if (!(doFeat && nextGated)) xout[tok*DD + d] = o;
        if (fin)  out[tok*DD + d] = o + 0.01f*resg[0]*(o - seq[tok*DD + d]);
        if (doFeat && nextGated) sprev[r][d] = g_prev[nextL][tok*DD + d];
    }
    if (!doFeat) return;
    __syncthreads();

    // fused pool partials (only on p0/l3 launch): sum the block's 4 rows
    if (doPool && tid < 64) {
        float ps = so[0][tid] + so[1][tid] + so[2][tid] + so[3][tid];
        atomicAdd(&g_poolacc[b*DD + tid], ps);
    }

    // ------- fused next-layer feature build -------
    float xfeat = 0.f;
    if (nextGated) {
        // stage W x-half into dead smem (64 rows x 64 cols, pad 76)
        const float* Wg = W_fb + nextL*DD*2*DD;
        #pragma unroll
        for (int i = tid; i < 64*64; i += 512)
            sWh[(i>>6)*76 + (i&63)] = Wg[(i>>6)*128 + (i&63)];
        __syncthreads();
        float acc = 0.f;
        if (tid < 256) {
            acc = b_fb[nextL*DD + d];
            const float4* Wr = (const float4*)&sWh[d*76];
            const float4* xr4 = (const float4*)&so[rr][0];
            #pragma unroll
            for (int q2 = 0; q2 < 16; ++q2) {
                float4 wv = Wr[q2], vv = xr4[q2];
                acc += wv.x*vv.x + wv.y*vv.y + wv.z*vv.z + wv.w*vv.w;
            }
        }
        __syncthreads();
        // stage W prev-half
        #pragma unroll
        for (int i = tid; i < 64*64; i += 512)
            sWh[(i>>6)*76 + (i&63)] = Wg[(i>>6)*128 + 64 + (i&63)];
        __syncthreads();
        if (tid < 256) {
            const float4* Wr = (const float4*)&sWh[d*76];
            const float4* pr4 = (const float4*)&sprev[rr][0];
            #pragma unroll
            for (int q2 = 0; q2 < 16; ++q2) {
                float4 wv = Wr[q2], vv = pr4[q2];
                acc += wv.x*vv.x + wv.y*vv.y + wv.z*vv.z + wv.w*vv.w;
            }
            float g = 1.f/(1.f + __expf(-acc));
            xfeat = so[rr][d]*g + sprev[rr][d]*(1.f - g);
            int tok = b*TT + rowBase + rr;
            xout[tok*DD + d] = xfeat;
        }
    } else {
        xfeat = so[rr][d];
    }

    // simplex projection per token (dims of token rr live in 2 warps)
    float sp = fmaxf(xfeat, 0.f) + log1pf(__expf(-fabsf(xfeat)));
    int half = (d >> 5) & 1;
    float v1 = sp;
    #pragma unroll
    for (int o = 16; o; o >>= 1) v1 += __shfl_xor_sync(0xffffffffu, v1, o);
    if (tid < 256 && (tid & 31) == 0) sred[r][half] = v1;
    __syncthreads();
    float s1 = sred[rr][0] + sred[rr][1] + EPSF;
    float sfrac = fmaxf(sp/s1, EPSF);
    float v2 = sfrac;
    #pragma unroll
    for (int o = 16; o; o >>= 1) v2 += __shfl_xor_sync(0xffffffffu, v2, o);
    if (tid < 256 && (tid & 31) == 0) sred[r][2 + half] = v2;
    __syncthreads();
    float s2 = sred[rr][2] + sred[rr][3] + EPSF;
    float pfin = sfrac/s2;

    if (tid < 256) {
        float u = sqrtf(pfin);
        su[d][r] = u;
        sv[d][r] = C2F/u;
    }
    __syncthreads();

    // write packed features for the block's 4 tokens
    if (tid < 256) {
        int dp = tid >> 2, tk = tid & 3;
        int d0 = 2*dp, d1 = 2*dp + 1;
        float f0 = (d0 < 64) ? su[d0][tk] : sv[d0-64][tk];
        float f1 = (d1 < 64) ? su[d1][tk] : sv[d1-64][tk];
        g_featP[dp*NTOK + b*TT + rowBase + tk] = make_float2(f0, f1);
    }

    // ------- last-block pool MLP (doPool launch only) -------
    if (doPool) {
        if (tid == 0) {
            __threadfence();
            int old = atomicAdd(&g_cnt, 1);
            sIsLast = (old == 255) ? 1 : 0;
        }
        __syncthreads();
        if (sIsLast) {
            __threadfence();
            // reuse smem: pooled/h1/hb/agg/comb/nb carved from so/sprev/su/sv
            float (*pooled)[DD] = (float(*)[DD])&so[0][0];     // 2x64
            float (*h1)[HH]     = (float(*)[HH])&so[2][0];     // 2x32
            float (*hb)[DD]     = (float(*)[DD])&sprev[0][0];  // 2x64
            float* agg  = &sprev[2][0];                        // 64
            float* comb = (float*)&su[0][0];                   // 128 (su has 320)
            float* nb   = (float*)&sv[0][0];                   // 64
            __syncthreads();
            if (tid < 128) pooled[tid>>6][tid&63] = g_poolacc[tid] * (1.f/TT);
            __syncthreads();
            if (tid < BB*HH) {
                int bb = tid / HH, h = tid - bb*HH;
                float a = bc1[h];
                #pragma unroll 8
                for (int k = 0; k < DD; ++k) a = fmaf(pooled[bb][k], Wc1[h*DD + k], a);
                h1[bb][h] = tanhf(a);
            }
            __syncthreads();
            if (tid < 128) {
                int bb = tid >> 6, dd = tid & 63;
                float a = bc2[dd];
                #pragma unroll 8
                for (int k = 0; k < HH; ++k) a = fmaf(h1[bb][k], Wc2[dd*HH + k], a);
                hb[bb][dd] = tanhf(a);
            }
            __syncthreads();
            if (tid < DD) {
                float a = 0.5f*(hb[0][tid] + hb[1][tid]);
                agg[tid]      = a;
                comb[tid]     = g_basin[tid];
                comb[DD+tid]  = a;
            }
            __syncthreads();
            if (tid < DD) {
                float a = bu[tid];
                #pragma unroll 8
                for (int k = 0; k < 2*DD; ++k) a = fmaf(Wu[tid*2*DD + k], comb[k], a);
                float g = 1.f/(1.f + expf(-a));
                nb[tid] = g_basin[tid]*(1.f - g) + agg[tid]*g;
                g_basin[tid] = nb[tid];
            }
            __syncthreads();
            if (tid < LAYERS) {
                float acc = b_temp[tid];
                #pragma unroll 8
                for (int k = 0; k < DD; ++k) acc = fmaf(W_temp[tid*DD + k], nb[k], acc);
                g_temps[tid] = 1.f/(1.f + expf(-acc)) + 0.5f;
            }
        }
    }
}

// ---------------------------------------------------------------------------
extern "C" void kernel_launch(void* const* d_in, const int* in_sizes, int n_in,
                              void* d_out, int out_size) {
    const float* basin_seq    = (const float*)d_in[0];
    const float* basin_coords = (const float*)d_in[1];
    const float* W_temp       = (const float*)d_in[2];
    const float* b_temp       = (const float*)d_in[3];
    const float* res_scale    = (const float*)d_in[4];
    const float* W_fb         = (const float*)d_in[5];
    const float* b_fb         = (const float*)d_in[6];
    const float* Wc1          = (const float*)d_in[7];
    const float* bc1          = (const float*)d_in[8];
    const float* Wc2          = (const float*)d_in[9];
    const float* bc2          = (const float*)d_in[10];
    const float* Wu           = (const float*)d_in[11];
    const float* bu           = (const float*)d_in[12];
    const float* res_g        = (const float*)d_in[13];

    k_feat0<<<NTOK/16, 512>>>(basin_seq, basin_coords, W_temp, b_temp, res_scale);

    int cursel = 0;
    for (int p = 0; p < 2; ++p) {
        for (int l = 0; l < LAYERS; ++l) {
            int last = (p == 1 && l == LAYERS-1);
            int doFeat = !last;
            int nextGated = (p == 1) || (l == LAYERS-1);
            int nextL = (l + 1) & 3;
            int doPool = (p == 0 && l == LAYERS-1) ? 1 : 0;
            k_attn<<<NTOK/4, 512>>>(cursel, l, p == 0 ? 1 : 0, last, doFeat,
                                    nextGated, nextL, doPool, W_fb, b_fb,
                                    basin_seq, res_g, (float*)d_out,
                                    Wc1, bc1, Wc2, bc2, Wu, bu, W_temp, b_temp);
            cursel ^= 1;
        }
    }
}

// round 16
// speedup vs baseline: 1.0623x; 1.0053x over previous
#include <cuda_runtime.h>
#include <math.h>

#define BB 2
#define TT 512
#define DD 64
#define LAYERS 4
#define HH 32
#define NTOK (BB*TT)
#define FDIM 128            // u (64) + v (64)
#define EPSF 1e-8f
#define C2F 7.0710678e-5f   // sqrt(EPS/2)

typedef unsigned long long u64;
typedef unsigned int u32;

__device__ float g_bufA[NTOK*DD];
__device__ float g_bufB[NTOK*DD];
__device__ float g_prev[LAYERS][NTOK*DD];
__device__ float2 g_featP[(FDIM/2)*NTOK];   // [dimpair][token] packed
__device__ float g_basin[DD];
__device__ float g_temps[LAYERS];
__device__ float g_res[LAYERS];
__device__ float g_poolacc[BB*DD];

__device__ __forceinline__ u64 pack2(float x, float y) {
    u64 r;
    asm("mov.b64 %0, {%1, %2};" : "=l"(r) : "r"(__float_as_uint(x)), "r"(__float_as_uint(y)));
    return r;
}
__device__ __forceinline__ u64 bcast2(float x) { return pack2(x, x); }
__device__ __forceinline__ void fma2(u64& d, u64 a, u64 b) {
    asm("fma.rn.f32x2 %0, %1, %2, %0;" : "+l"(d) : "l"(a), "l"(b));
}
__device__ __forceinline__ void unpack2(u64 v, float& lo, float& hi) {
    u32 a, b;
    asm("mov.b64 {%0, %1}, %2;" : "=r"(a), "=r"(b) : "l"(v));
    lo = __uint_as_float(a); hi = __uint_as_float(b);
}

// acos for x in [-1,1], |err| ~2e-8 (A&S 4.4.45)
__device__ __forceinline__ float acos_fast(float x) {
    float ax = fabsf(x);
    float r = sqrtf(1.0f - ax);
    float p = fmaf(ax, -0.0012624911f, 0.0066700901f);
    p = fmaf(ax, p, -0.0170881256f);
    p = fmaf(ax, p, 0.0308918810f);
    p = fmaf(ax, p, -0.0501743046f);
    p = fmaf(ax, p, 0.0889789874f);
    p = fmaf(ax, p, -0.2145988016f);
    p = fmaf(ax, p, 1.5707963050f);
    float res = r * p;
    return (x < 0.f) ? (3.14159265358979f - res) : res;
}

// ---------------------------------------------------------------------------
// feat0: copy src -> bufA, init basin/temps/res/poolacc, build packed
// features for pass0/layer0. 16 tokens/block, warp = token, grid 64.
__global__ void __launch_bounds__(512) k_feat0(
        const float* __restrict__ src,
        const float* __restrict__ basin_coords,
        const float* __restrict__ W_temp,
        const float* __restrict__ b_temp,
        const float* __restrict__ res_scale) {
    int tid = threadIdx.x;
    int wid = tid >> 5, c = tid & 31;
    int tok0 = blockIdx.x * 16;
    int tok = tok0 + wid;

    __shared__ float sfeat[FDIM][17];

    if (blockIdx.x == 0) {
        if (wid == 0) {
            g_basin[c]      = basin_coords[c];
            g_basin[c + 32] = basin_coords[c + 32];
            if (c < LAYERS) {
                g_res[c] = res_scale[c];
                float acc = b_temp[c];
                #pragma unroll 8
                for (int d2 = 0; d2 < DD; ++d2)
                    acc = fmaf(W_temp[c*DD + d2], basin_coords[d2], acc);
                g_temps[c] = 1.f/(1.f + expf(-acc)) + 0.5f;
            }
        }
        if (tid >= 128 && tid < 256) g_poolacc[tid - 128] = 0.f;
    }

    float xn0 = src[tok*64 + c];
    float xn1 = src[tok*64 + c + 32];
    g_bufA[tok*64 + c]      = xn0;
    g_bufA[tok*64 + c + 32] = xn1;

    float sp0 = fmaxf(xn0, 0.f) + log1pf(__expf(-fabsf(xn0)));
    float sp1 = fmaxf(xn1, 0.f) + log1pf(__expf(-fabsf(xn1)));

    float v = sp0 + sp1;
    #pragma unroll
    for (int o = 16; o; o >>= 1) v += __shfl_xor_sync(0xffffffffu, v, o);
    float s1 = v + EPSF;
    float q0 = fmaxf(sp0/s1, EPSF), q1 = fmaxf(sp1/s1, EPSF);
    v = q0 + q1;
    #pragma unroll
    for (int o = 16; o; o >>= 1) v += __shfl_xor_sync(0xffffffffu, v, o);
    float s2 = v + EPSF;
    float p0 = q0/s2, p1 = q1/s2;

    float u0 = sqrtf(p0), u1 = sqrtf(p1);
    sfeat[c][wid]       = u0;
    sfeat[c+32][wid]    = u1;
    sfeat[64+c][wid]    = C2F/u0;
    sfeat[96+c][wid]    = C2F/u1;
    __syncthreads();

    // packed transposed store: dim-pair major, 16 tokens contiguous
    #pragma unroll
    for (int i = tid; i < (FDIM/2)*16; i += 512) {
        int dp = i >> 4, t = i & 15;
        g_featP[dp*NTOK + tok0 + t] = make_float2(sfeat[2*dp][t], sfeat[2*dp+1][t]);
    }
}

// ---------------------------------------------------------------------------
// attention + fused next-layer feature build (+ fused pool partials).
// 4 rows/block, grid 256, 512 threads, 2 blocks/SM.
// NOTE: no block barrier between phase 1 and phase 3 — warp w's phase-3
// j-range [w*32, w*32+32) reads only LePr entries written by warp w itself,
// so __syncwarp() suffices (wSum is consumed after the phase-3 barrier).
__global__ void __launch_bounds__(512, 2)
k_attn(int cursel, int l, int snap, int fin, int doFeat, int nextGated, int nextL,
       int doPool,
       const float* __restrict__ W_fb, const float* __restrict__ b_fb,
       const float* __restrict__ seq, const float* __restrict__ resg,
       float* __restrict__ out) {
    const float* xin = cursel ? g_bufB : g_bufA;
    float*       xout = cursel ? g_bufA : g_bufB;

    int blk = blockIdx.x;
    int b = blk >> 7;
    int rowBase = (blk & 127) << 2;
    int tid = threadIdx.x, w = tid >> 5, c = tid & 31;

    // blob: LePr (8K) | wFA (8K) | wFB (8K). sWh (GEMV stage, 19456B) aliases
    // LePr+wFA+start of wFB, all dead by the time the epilogue GEMV runs.
    __shared__ __align__(16) char smemBlob[24576];
    u64 (*LePr)[2]     = (u64(*)[2])(smemBlob);            // [TT][rowpair]
    u64 (*wFA)[2][32]  = (u64(*)[2][32])(smemBlob + 8192);
    u64 (*wFB)[2][32]  = (u64(*)[2][32])(smemBlob + 16384);
    float* sWh         = (float*)smemBlob;                 // [64][76]

    __shared__ __align__(16) u64 rf2s[FDIM][2];   // [dim][rowpair] packed rows
    __shared__ float so[4][64], sprev[4][64];
    __shared__ float su[64][5], sv[64][5];
    __shared__ float wSum[16][4];
    __shared__ float sred[4][4];

    float nInvT = -1.f / fmaxf(g_temps[l], 1e-6f);

    // stage row features: thread = (dim dd, rowpair rp)
    if (tid < 256) {
        int dd = tid >> 1, rp = tid & 1;
        const float* gfp = (const float*)g_featP;
        int base = (dd >> 1)*(2*NTOK) + (dd & 1);
        int t0 = b*TT + rowBase + 2*rp;
        float f0 = gfp[base + 2*t0];
        float f1 = gfp[base + 2*(t0+1)];
        rf2s[dd][rp] = pack2(f0, f1);
    }
    __syncthreads();

    // phase 1: 128-dot for this lane's j, 4 rows via 2 packed accumulators
    // (4-in-flight float2 prefetch — measured-best configuration)
    int jl = w*32 + c;
    const float2* fp = g_featP + b*TT + jl;
    u64 acc0 = 0ull, acc1 = 0ull;
    float2 jv[4], jvn[4];
    #pragma unroll
    for (int q = 0; q < 4; ++q) { jv[q] = fp[q*NTOK]; jvn[q] = make_float2(0.f, 0.f); }
    #pragma unroll 1
    for (int dp0 = 0; dp0 < FDIM/2; dp0 += 4) {
        if (dp0 + 4 < FDIM/2) {
            #pragma unroll
            for (int q = 0; q < 4; ++q) jvn[q] = fp[(dp0+4+q)*NTOK];
        }
        #pragma unroll
        for (int q = 0; q < 4; ++q) {
            int dp = dp0 + q;
            const ulonglong2 rA = *(const ulonglong2*)&rf2s[2*dp][0];
            const ulonglong2 rB = *(const ulonglong2*)&rf2s[2*dp+1][0];
            u64 jx = bcast2(jv[q].x);
            u64 jy = bcast2(jv[q].y);
            fma2(acc0, rA.x, jx);
            fma2(acc1, rA.y, jx);
            fma2(acc0, rB.x, jy);
            fma2(acc1, rB.y, jy);
        }
        #pragma unroll
        for (int q = 0; q < 4; ++q) jv[q] = jvn[q];
    }

    // e = exp(2*acos(clip)*nInvT) (no-max softmax: logits in [-12.6, 0])
    float i0, i1, i2, i3;
    unpack2(acc0, i0, i1);
    unpack2(acc1, i2, i3);
    i0 = fminf(fmaxf(i0, -1.f + 1e-6f), 1.f - 1e-6f);
    i1 = fminf(fmaxf(i1, -1.f + 1e-6f), 1.f - 1e-6f);
    i2 = fminf(fmaxf(i2, -1.f + 1e-6f), 1.f - 1e-6f);
    i3 = fminf(fmaxf(i3, -1.f + 1e-6f), 1.f - 1e-6f);
    float e0 = __expf(2.f*acos_fast(i0)*nInvT);
    float e1 = __expf(2.f*acos_fast(i1)*nInvT);
    float e2 = __expf(2.f*acos_fast(i2)*nInvT);
    float e3 = __expf(2.f*acos_fast(i3)*nInvT);
    {
        ulonglong2 ev;
        ev.x = pack2(e0, e1);
        ev.y = pack2(e2, e3);
        *(ulonglong2*)&LePr[jl][0] = ev;
    }
    float es[4] = {e0, e1, e2, e3};
    #pragma unroll
    for (int r = 0; r < 4; ++r) {
        float sv2 = es[r];
        #pragma unroll
        for (int o = 16; o; o >>= 1) sv2 += __shfl_xor_sync(0xffffffffu, sv2, o);
        if (c == 0) wSum[w][r] = sv2;
    }
    __syncwarp();   // warp-local: phase 3 reads only this warp's LePr entries

    // phase 3: value accumulation, 16 warps x 32 j, 1-ahead prefetch
    {
        u64 fA0 = 0ull, fA1 = 0ull, fB0 = 0ull, fB1 = 0ull;
        const float2* xb2 = (const float2*)(xin + b*TT*DD);
        int j0 = w*32;
        float2 xv = xb2[j0*32 + c];
        #pragma unroll 4
        for (int jj = 0; jj < 32; ++jj) {
            int j = j0 + jj;
            float2 nx = make_float2(0.f, 0.f);
            if (jj < 31) nx = xb2[(j+1)*32 + c];
            ulonglong2 ep = *(const ulonglong2*)&LePr[j][0];
            u64 xA = bcast2(xv.x), xB = bcast2(xv.y);
            fma2(fA0, ep.x, xA);
            fma2(fA1, ep.y, xA);
            fma2(fB0, ep.x, xB);
            fma2(fB1, ep.y, xB);
            xv = nx;
        }
        wFA[w][0][c] = fA0; wFA[w][1][c] = fA1;
        wFB[w][0][c] = fB0; wFB[w][1][c] = fB1;
    }
    __syncthreads();

    // merge: thread = (row r, dim d), 256 threads
    int r = tid >> 6, d = tid & 63;
    int rr = r & 3;
    if (tid < 256) {
        int q = r >> 1, sel = r & 1;
        int cc = d >> 1, ab = d & 1;
        float F = 0.f, S = 0.f;
        #pragma unroll
        for (int ww = 0; ww < 16; ++ww) {
            u64 fp2 = ab ? wFB[ww][q][cc] : wFA[ww][q][cc];
            float lo, hi;
            unpack2(fp2, lo, hi);
            F += sel ? hi : lo;
            S += wSum[ww][r];
        }
        int tok = b*TT + rowBase + r;
        float rs = g_res[l];
        float xv = xin[tok*DD + d];
        float o = xv + rs*(F/S - xv);
        so[r][d] = o;
        if (snap) g_prev[l][tok*DD + d] = o;
        if (!(doFeat && nextGated)) xout[tok*DD + d] = o;
        if (fin)  out[tok*DD + d] = o + 0.01f*resg[0]*(o - seq[tok*DD + d]);
        if (doFeat && nextGated) sprev[r][d] = g_prev[nextL][tok*DD + d];
    }
    if (!doFeat) return;
    __syncthreads();

    // fused pool partials (only on p0/l3 launch): sum the block's 4 rows
    if (doPool && tid < 64) {
        float ps = so[0][tid] + so[1][tid] + so[2][tid] + so[3][tid];
        atomicAdd(&g_poolacc[b*DD + tid], ps);
    }

    // ------- fused next-layer feature build -------
    float xfeat = 0.f;
    if (nextGated) {
        // stage W x-half into dead smem (64 rows x 64 cols, pad 76)
        const float* Wg = W_fb + nextL*DD*2*DD;
        #pragma unroll
        for (int i = tid; i < 64*64; i += 512)
            sWh[(i>>6)*76 + (i&63)] = Wg[(i>>6)*128 + (i&63)];
        __syncthreads();
        float acc = 0.f;
        if (tid < 256) {
            acc = b_fb[nextL*DD + d];
            const float4* Wr = (const float4*)&sWh[d*76];
            const float4* xr4 = (const float4*)&so[rr][0];
            #pragma unroll
            for (int q2 = 0; q2 < 16; ++q2) {
                float4 wv = Wr[q2], vv = xr4[q2];
                acc += wv.x*vv.x + wv.y*vv.y + wv.z*vv.z + wv.w*vv.w;
            }
        }
        __syncthreads();
        // stage W prev-half
        #pragma unroll
        for (int i = tid; i < 64*64; i += 512)
            sWh[(i>>6)*76 + (i&63)] = Wg[(i>>6)*128 + 64 + (i&63)];
        __syncthreads();
        if (tid < 256) {
            const float4* Wr = (const float4*)&sWh[d*76];
            const float4* pr4 = (const float4*)&sprev[rr][0];
            #pragma unroll
            for (int q2 = 0; q2 < 16; ++q2) {
                float4 wv = Wr[q2], vv = pr4[q2];
                acc += wv.x*vv.x + wv.y*vv.y + wv.z*vv.z + wv.w*vv.w;
            }
            float g = 1.f/(1.f + __expf(-acc));
            xfeat = so[rr][d]*g + sprev[rr][d]*(1.f - g);
            int tok = b*TT + rowBase + rr;
            xout[tok*DD + d] = xfeat;
        }
    } else {
        xfeat = so[rr][d];
    }

    // simplex projection per token (dims of token rr live in 2 warps)
    float sp = fmaxf(xfeat, 0.f) + log1pf(__expf(-fabsf(xfeat)));
    int half = (d >> 5) & 1;
    float v1 = sp;
    #pragma unroll
    for (int o = 16; o; o >>= 1) v1 += __shfl_xor_sync(0xffffffffu, v1, o);
    if (tid < 256 && (tid & 31) == 0) sred[r][half] = v1;
    __syncthreads();
    float s1 = sred[rr][0] + sred[rr][1] + EPSF;
    float sfrac = fmaxf(sp/s1, EPSF);
    float v2 = sfrac;
    #pragma unroll
    for (int o = 16; o; o >>= 1) v2 += __shfl_xor_sync(0xffffffffu, v2, o);
    if (tid < 256 && (tid & 31) == 0) sred[r][2 + half] = v2;
    __syncthreads();
    float s2 = sred[rr][2] + sred[rr][3] + EPSF;
    float pfin = sfrac/s2;

    if (tid < 256) {
        float u = sqrtf(pfin);
        su[d][r] = u;
        sv[d][r] = C2F/u;
    }
    __syncthreads();

    // write packed features for the block's 4 tokens
    if (tid < 256) {
        int dp = tid >> 2, tk = tid & 3;
        int d0 = 2*dp, d1 = 2*dp + 1;
        float f0 = (d0 < 64) ? su[d0][tk] : sv[d0-64][tk];
        float f1 = (d1 < 64) ? su[d1][tk] : sv[d1-64][tk];
        g_featP[dp*NTOK + b*TT + rowBase + tk] = make_float2(f0, f1);
    }
}

// ---------------------------------------------------------------------------
// pool MLP only — pooled sums come from fused atomics in k_attn(p0,l3).
__global__ void __launch_bounds__(128) k_pool(
                       const float* __restrict__ Wc1, const float* __restrict__ bc1,
                       const float* __restrict__ Wc2, const float* __restrict__ bc2,
                       const float* __restrict__ Wu,  const float* __restrict__ bu,
                       const float* __restrict__ W_temp, const float* __restrict__ b_temp) {
    int tid = threadIdx.x;
    __shared__ float pooled[BB][DD];
    __shared__ float h1[BB][HH];
    __shared__ float hb[BB][DD];
    __shared__ float agg[DD], comb[2*DD], nb[DD];

    pooled[tid>>6][tid&63] = g_poolacc[tid] * (1.f/TT);
    __syncthreads();
    if (tid < BB*HH) {
        int bb = tid / HH, h = tid - bb*HH;
        float a = bc1[h];
        #pragma unroll 8
        for (int k = 0; k < DD; ++k) a = fmaf(pooled[bb][k], Wc1[h*DD + k], a);
        h1[bb][h] = tanhf(a);
    }
    __syncthreads();
    {
        int b = tid >> 6, d = tid & 63;
        float a = bc2[d];
        #pragma unroll 8
        for (int k = 0; k < HH; ++k) a = fmaf(h1[b][k], Wc2[d*HH + k], a);
        hb[b][d] = tanhf(a);
    }
    __syncthreads();
    if (tid < DD) {
        float a = 0.5f*(hb[0][tid] + hb[1][tid]);
        agg[tid]      = a;
        comb[tid]     = g_basin[tid];
        comb[DD+tid]  = a;
    }
    __syncthreads();
    if (tid < DD) {
        float a = bu[tid];
        #pragma unroll 8
        for (int k = 0; k < 2*DD; ++k) a = fmaf(Wu[tid*2*DD + k], comb[k], a);
        float g = 1.f/(1.f + expf(-a));
        nb[tid] = g_basin[tid]*(1.f - g) + agg[tid]*g;
        g_basin[tid] = nb[tid];
    }
    __syncthreads();
    if (tid < LAYERS) {
        float acc = b_temp[tid];
        #pragma unroll 8
        for (int k = 0; k < DD; ++k) acc = fmaf(W_temp[tid*DD + k], nb[k], acc);
        g_temps[tid] = 1.f/(1.f + expf(-acc)) + 0.5f;
    }
}

// ---------------------------------------------------------------------------
extern "C" void kernel_launch(void* const* d_in, const int* in_sizes, int n_in,
                              void* d_out, int out_size) {
    const float* basin_seq    = (const float*)d_in[0];
    const float* basin_coords = (const float*)d_in[1];
    const float* W_temp       = (const float*)d_in[2];
    const float* b_temp       = (const float*)d_in[3];
    const float* res_scale    = (const float*)d_in[4];
    const float* W_fb         = (const float*)d_in[5];
    const float* b_fb         = (const float*)d_in[6];
    const float* Wc1          = (const float*)d_in[7];
    const float* bc1          = (const float*)d_in[8];
    const float* Wc2          = (const float*)d_in[9];
    const float* bc2          = (const float*)d_in[10];
    const float* Wu           = (const float*)d_in[11];
    const float* bu           = (const float*)d_in[12];
    const float* res_g        = (const float*)d_in[13];

    k_feat0<<<NTOK/16, 512>>>(basin_seq, basin_coords, W_temp, b_temp, res_scale);

    int cursel = 0;
    for (int p = 0; p < 2; ++p) {
        for (int l = 0; l < LAYERS; ++l) {
            int last = (p == 1 && l == LAYERS-1);
            int doFeat = !last;
            int nextGated = (p == 1) || (l == LAYERS-1);
            int nextL = (l + 1) & 3;
            int doPool = (p == 0 && l == LAYERS-1) ? 1 : 0;
            k_attn<<<NTOK/4, 512>>>(cursel, l, p == 0 ? 1 : 0, last, doFeat,
                                    nextGated, nextL, doPool, W_fb, b_fb,
                                    basin_seq, res_g, (float*)d_out);
            cursel ^= 1;
            if (p == 0 && l == LAYERS-1) {
                k_pool<<<1, 128>>>(Wc1, bc1, Wc2, bc2, Wu, bu, W_temp, b_temp);
            }
        }
    }
}

// round 17
// speedup vs baseline: 1.0875x; 1.0238x over previous
#include <cuda_runtime.h>
#include <math.h>

#define BB 2
#define TT 512
#define DD 64
#define LAYERS 4
#define HH 32
#define NTOK (BB*TT)
#define FDIM 128            // u (64) + v (64)
#define EPSF 1e-8f
#define C2F 7.0710678e-5f   // sqrt(EPS/2)

typedef unsigned long long u64;
typedef unsigned int u32;

__device__ float g_bufA[NTOK*DD];
__device__ float g_bufB[NTOK*DD];
__device__ float g_prev[LAYERS][NTOK*DD];
__device__ float2 g_featP[(FDIM/2)*NTOK];   // [dimpair][token] packed
__device__ float g_basin[DD];
__device__ float g_temps[LAYERS];
__device__ float g_res[LAYERS];
__device__ float g_poolacc[BB*DD];

__device__ __forceinline__ u64 pack2(float x, float y) {
    u64 r;
    asm("mov.b64 %0, {%1, %2};" : "=l"(r) : "r"(__float_as_uint(x)), "r"(__float_as_uint(y)));
    return r;
}
__device__ __forceinline__ u64 bcast2(float x) { return pack2(x, x); }
__device__ __forceinline__ void fma2(u64& d, u64 a, u64 b) {
    asm("fma.rn.f32x2 %0, %1, %2, %0;" : "+l"(d) : "l"(a), "l"(b));
}
__device__ __forceinline__ void unpack2(u64 v, float& lo, float& hi) {
    u32 a, b;
    asm("mov.b64 {%0, %1}, %2;" : "=r"(a), "=r"(b) : "l"(v));
    lo = __uint_as_float(a); hi = __uint_as_float(b);
}

// acos for x in [-1,1], |err| ~2e-8 (A&S 4.4.45)
__device__ __forceinline__ float acos_fast(float x) {
    float ax = fabsf(x);
    float r = sqrtf(1.0f - ax);
    float p = fmaf(ax, -0.0012624911f, 0.0066700901f);
    p = fmaf(ax, p, -0.0170881256f);
    p = fmaf(ax, p, 0.0308918810f);
    p = fmaf(ax, p, -0.0501743046f);
    p = fmaf(ax, p, 0.0889789874f);
    p = fmaf(ax, p, -0.2145988016f);
    p = fmaf(ax, p, 1.5707963050f);
    float res = r * p;
    return (x < 0.f) ? (3.14159265358979f - res) : res;
}

// ---------------------------------------------------------------------------
// feat0: copy src -> bufA, init basin/temps/res/poolacc, build packed
// features for pass0/layer0. 8 tokens/block, 256 threads, grid 128
// (covers ~all SMs instead of 64).
__global__ void __launch_bounds__(256) k_feat0(
        const float* __restrict__ src,
        const float* __restrict__ basin_coords,
        const float* __restrict__ W_temp,
        const float* __restrict__ b_temp,
        const float* __restrict__ res_scale) {
    int tid = threadIdx.x;
    int wid = tid >> 5, c = tid & 31;
    int tok0 = blockIdx.x * 8;
    int tok = tok0 + wid;

    __shared__ float sfeat[FDIM][9];

    if (blockIdx.x == 0) {
        if (wid == 0) {
            g_basin[c]      = basin_coords[c];
            g_basin[c + 32] = basin_coords[c + 32];
            if (c < LAYERS) {
                g_res[c] = res_scale[c];
                float acc = b_temp[c];
                #pragma unroll 8
                for (int d2 = 0; d2 < DD; ++d2)
                    acc = fmaf(W_temp[c*DD + d2], basin_coords[d2], acc);
                g_temps[c] = 1.f/(1.f + expf(-acc)) + 0.5f;
            }
        }
        if (tid >= 128 && tid < 256) g_poolacc[tid - 128] = 0.f;
    }

    float xn0 = src[tok*64 + c];
    float xn1 = src[tok*64 + c + 32];
    g_bufA[tok*64 + c]      = xn0;
    g_bufA[tok*64 + c + 32] = xn1;

    float sp0 = fmaxf(xn0, 0.f) + log1pf(__expf(-fabsf(xn0)));
    float sp1 = fmaxf(xn1, 0.f) + log1pf(__expf(-fabsf(xn1)));

    float v = sp0 + sp1;
    #pragma unroll
    for (int o = 16; o; o >>= 1) v += __shfl_xor_sync(0xffffffffu, v, o);
    float s1 = v + EPSF;
    float q0 = fmaxf(sp0/s1, EPSF), q1 = fmaxf(sp1/s1, EPSF);
    v = q0 + q1;
    #pragma unroll
    for (int o = 16; o; o >>= 1) v += __shfl_xor_sync(0xffffffffu, v, o);
    float s2 = v + EPSF;
    float p0 = q0/s2, p1 = q1/s2;

    float u0 = sqrtf(p0), u1 = sqrtf(p1);
    sfeat[c][wid]       = u0;
    sfeat[c+32][wid]    = u1;
    sfeat[64+c][wid]    = C2F/u0;
    sfeat[96+c][wid]    = C2F/u1;
    __syncthreads();

    // packed transposed store: dim-pair major, 8 tokens contiguous
    #pragma unroll
    for (int i = tid; i < (FDIM/2)*8; i += 256) {
        int dp = i >> 3, t = i & 7;
        g_featP[dp*NTOK + tok0 + t] = make_float2(sfeat[2*dp][t], sfeat[2*dp+1][t]);
    }
}

// ---------------------------------------------------------------------------
// attention + fused next-layer feature build (+ fused pool partials).
// 4 rows/block, grid 256, 512 threads, 2 blocks/SM.
// No block barrier between phase 1 and phase 3 (warp-local dependency).
// Gated epilogue stages the full 64x128 W in ONE pass (blob enlarged).
__global__ void __launch_bounds__(512, 2)
k_attn(int cursel, int l, int snap, int fin, int doFeat, int nextGated, int nextL,
       int doPool,
       const float* __restrict__ W_fb, const float* __restrict__ b_fb,
       const float* __restrict__ seq, const float* __restrict__ resg,
       float* __restrict__ out) {
    const float* xin = cursel ? g_bufB : g_bufA;
    float*       xout = cursel ? g_bufA : g_bufB;

    int blk = blockIdx.x;
    int b = blk >> 7;
    int rowBase = (blk & 127) << 2;
    int tid = threadIdx.x, w = tid >> 5, c = tid & 31;

    // blob: LePr (8K) | wFA (8K) | wFB (8K) during attention phases.
    // sWh (full-W GEMV stage, 64 rows x 132 floats = 33792B) aliases the
    // whole blob; all prior occupants are dead before the epilogue GEMV.
    __shared__ __align__(16) char smemBlob[33792];
    u64 (*LePr)[2]     = (u64(*)[2])(smemBlob);            // [TT][rowpair]
    u64 (*wFA)[2][32]  = (u64(*)[2][32])(smemBlob + 8192);
    u64 (*wFB)[2][32]  = (u64(*)[2][32])(smemBlob + 16384);
    float* sWh         = (float*)smemBlob;                 // [64][132]

    __shared__ __align__(16) u64 rf2s[FDIM][2];   // [dim][rowpair] packed rows
    __shared__ float so[4][64], sprev[4][64];
    __shared__ float su[64][5], sv[64][5];
    __shared__ float wSum[16][4];
    __shared__ float sred[4][4];

    float nInvT = -1.f / fmaxf(g_temps[l], 1e-6f);

    // stage row features: thread = (dim dd, rowpair rp)
    if (tid < 256) {
        int dd = tid >> 1, rp = tid & 1;
        const float* gfp = (const float*)g_featP;
        int base = (dd >> 1)*(2*NTOK) + (dd & 1);
        int t0 = b*TT + rowBase + 2*rp;
        float f0 = gfp[base + 2*t0];
        float f1 = gfp[base + 2*(t0+1)];
        rf2s[dd][rp] = pack2(f0, f1);
    }
    __syncthreads();

    // phase 1: 128-dot for this lane's j, 4 rows via 2 packed accumulators
    // (4-in-flight float2 prefetch — measured-best configuration)
    int jl = w*32 + c;
    const float2* fp = g_featP + b*TT + jl;
    u64 acc0 = 0ull, acc1 = 0ull;
    float2 jv[4], jvn[4];
    #pragma unroll
    for (int q = 0; q < 4; ++q) { jv[q] = fp[q*NTOK]; jvn[q] = make_float2(0.f, 0.f); }
    #pragma unroll 1
    for (int dp0 = 0; dp0 < FDIM/2; dp0 += 4) {
        if (dp0 + 4 < FDIM/2) {
            #pragma unroll
            for (int q = 0; q < 4; ++q) jvn[q] = fp[(dp0+4+q)*NTOK];
        }
        #pragma unroll
        for (int q = 0; q < 4; ++q) {
            int dp = dp0 + q;
            const ulonglong2 rA = *(const ulonglong2*)&rf2s[2*dp][0];
            const ulonglong2 rB = *(const ulonglong2*)&rf2s[2*dp+1][0];
            u64 jx = bcast2(jv[q].x);
            u64 jy = bcast2(jv[q].y);
            fma2(acc0, rA.x, jx);
            fma2(acc1, rA.y, jx);
            fma2(acc0, rB.x, jy);
            fma2(acc1, rB.y, jy);
        }
        #pragma unroll
        for (int q = 0; q < 4; ++q) jv[q] = jvn[q];
    }

    // e = exp(2*acos(clip)*nInvT) (no-max softmax: logits in [-12.6, 0])
    float i0, i1, i2, i3;
    unpack2(acc0, i0, i1);
    unpack2(acc1, i2, i3);
    i0 = fminf(fmaxf(i0, -1.f + 1e-6f), 1.f - 1e-6f);
    i1 = fminf(fmaxf(i1, -1.f + 1e-6f), 1.f - 1e-6f);
    i2 = fminf(fmaxf(i2, -1.f + 1e-6f), 1.f - 1e-6f);
    i3 = fminf(fmaxf(i3, -1.f + 1e-6f), 1.f - 1e-6f);
    float e0 = __expf(2.f*acos_fast(i0)*nInvT);
    float e1 = __expf(2.f*acos_fast(i1)*nInvT);
    float e2 = __expf(2.f*acos_fast(i2)*nInvT);
    float e3 = __expf(2.f*acos_fast(i3)*nInvT);
    {
        ulonglong2 ev;
        ev.x = pack2(e0, e1);
        ev.y = pack2(e2, e3);
        *(ulonglong2*)&LePr[jl][0] = ev;
    }
    float es[4] = {e0, e1, e2, e3};
    #pragma unroll
    for (int r = 0; r < 4; ++r) {
        float sv2 = es[r];
        #pragma unroll
        for (int o = 16; o; o >>= 1) sv2 += __shfl_xor_sync(0xffffffffu, sv2, o);
        if (c == 0) wSum[w][r] = sv2;
    }
    __syncwarp();   // warp-local: phase 3 reads only this warp's LePr entries

    // phase 3: value accumulation, 16 warps x 32 j, 1-ahead prefetch
    {
        u64 fA0 = 0ull, fA1 = 0ull, fB0 = 0ull, fB1 = 0ull;
        const float2* xb2 = (const float2*)(xin + b*TT*DD);
        int j0 = w*32;
        float2 xv = xb2[j0*32 + c];
        #pragma unroll 4
        for (int jj = 0; jj < 32; ++jj) {
            int j = j0 + jj;
            float2 nx = make_float2(0.f, 0.f);
            if (jj < 31) nx = xb2[(j+1)*32 + c];
            ulonglong2 ep = *(const ulonglong2*)&LePr[j][0];
            u64 xA = bcast2(xv.x), xB = bcast2(xv.y);
            fma2(fA0, ep.x, xA);
            fma2(fA1, ep.y, xA);
            fma2(fB0, ep.x, xB);
            fma2(fB1, ep.y, xB);
            xv = nx;
        }
        wFA[w][0][c] = fA0; wFA[w][1][c] = fA1;
        wFB[w][0][c] = fB0; wFB[w][1][c] = fB1;
    }
    __syncthreads();

    // merge: thread = (row r, dim d), 256 threads
    int r = tid >> 6, d = tid & 63;
    int rr = r & 3;
    if (tid < 256) {
        int q = r >> 1, sel = r & 1;
        int cc = d >> 1, ab = d & 1;
        float F = 0.f, S = 0.f;
        #pragma unroll
        for (int ww = 0; ww < 16; ++ww) {
            u64 fp2 = ab ? wFB[ww][q][cc] : wFA[ww][q][cc];
            float lo, hi;
            unpack2(fp2, lo, hi);
            F += sel ? hi : lo;
            S += wSum[ww][r];
        }
        int tok = b*TT + rowBase + r;
        float rs = g_res[l];
        float xv = xin[tok*DD + d];
        float o = xv + rs*(__fdividef(F, S) - xv);
        so[r][d] = o;
        if (snap) g_prev[l][tok*DD + d] = o;
        if (!(doFeat && nextGated)) xout[tok*DD + d] = o;
        if (fin)  out[tok*DD + d] = o + 0.01f*resg[0]*(o - seq[tok*DD + d]);
        if (doFeat && nextGated) sprev[r][d] = g_prev[nextL][tok*DD + d];
    }
    if (!doFeat) return;
    __syncthreads();

    // fused pool partials (only on p0/l3 launch): sum the block's 4 rows
    if (doPool && tid < 64) {
        float ps = so[0][tid] + so[1][tid] + so[2][tid] + so[3][tid];
        atomicAdd(&g_poolacc[b*DD + tid], ps);
    }

    // ------- fused next-layer feature build (single-pass W staging) -------
    float xfeat = 0.f;
    if (nextGated) {
        const float* Wg = W_fb + nextL*DD*2*DD;
        #pragma unroll
        for (int i = tid; i < 64*128; i += 512)
            sWh[(i>>7)*132 + (i&127)] = Wg[i];
        __syncthreads();
        if (tid < 256) {
            float acc = b_fb[nextL*DD + d];
            const float4* Wr = (const float4*)&sWh[d*132];
            const float4* xr4 = (const float4*)&so[rr][0];
            const float4* pr4 = (const float4*)&sprev[rr][0];
            #pragma unroll
            for (int q2 = 0; q2 < 16; ++q2) {
                float4 wv = Wr[q2], vv = xr4[q2];
                acc += wv.x*vv.x + wv.y*vv.y + wv.z*vv.z + wv.w*vv.w;
            }
            #pragma unroll
            for (int q2 = 0; q2 < 16; ++q2) {
                float4 wv = Wr[16+q2], vv = pr4[q2];
                acc += wv.x*vv.x + wv.y*vv.y + wv.z*vv.z + wv.w*vv.w;
            }
            float g = 1.f/(1.f + __expf(-acc));
            xfeat = so[rr][d]*g + sprev[rr][d]*(1.f - g);
            int tok = b*TT + rowBase + rr;
            xout[tok*DD + d] = xfeat;
        }
    } else {
        xfeat = so[rr][d];
    }

    // simplex projection per token (dims of token rr live in 2 warps)
    float sp = fmaxf(xfeat, 0.f) + log1pf(__expf(-fabsf(xfeat)));
    int half = (d >> 5) & 1;
    float v1 = sp;
    #pragma unroll
    for (int o = 16; o; o >>= 1) v1 += __shfl_xor_sync(0xffffffffu, v1, o);
    if (tid < 256 && (tid & 31) == 0) sred[r][half] = v1;
    __syncthreads();
    float s1 = sred[rr][0] + sred[rr][1] + EPSF;
    float sfrac = fmaxf(sp/s1, EPSF);
    float v2 = sfrac;
    #pragma unroll
    for (int o = 16; o; o >>= 1) v2 += __shfl_xor_sync(0xffffffffu, v2, o);
    if (tid < 256 && (tid & 31) == 0) sred[r][2 + half] = v2;
    __syncthreads();
    float s2 = sred[rr][2] + sred[rr][3] + EPSF;
    float pfin = sfrac/s2;

    if (tid < 256) {
        float u = sqrtf(pfin);
        su[d][r] = u;
        sv[d][r] = C2F/u;
    }
    __syncthreads();

    // write packed features for the block's 4 tokens
    if (tid < 256) {
        int dp = tid >> 2, tk = tid & 3;
        int d0 = 2*dp, d1 = 2*dp + 1;
        float f0 = (d0 < 64) ? su[d0][tk] : sv[d0-64][tk];
        float f1 = (d1 < 64) ? su[d1][tk] : sv[d1-64][tk];
        g_featP[dp*NTOK + b*TT + rowBase + tk] = make_float2(f0, f1);
    }
}

// ---------------------------------------------------------------------------
// pool MLP only — pooled sums come from fused atomics in k_attn(p0,l3).
__global__ void __launch_bounds__(128) k_pool(
                       const float* __restrict__ Wc1, const float* __restrict__ bc1,
                       const float* __restrict__ Wc2, const float* __restrict__ bc2,
                       const float* __restrict__ Wu,  const float* __restrict__ bu,
                       const float* __restrict__ W_temp, const float* __restrict__ b_temp) {
    int tid = threadIdx.x;
    __shared__ float pooled[BB][DD];
    __shared__ float h1[BB][HH];
    __shared__ float hb[BB][DD];
    __shared__ float agg[DD], comb[2*DD], nb[DD];

    pooled[tid>>6][tid&63] = g_poolacc[tid] * (1.f/TT);
    __syncthreads();
    if (tid < BB*HH) {
        int bb = tid / HH, h = tid - bb*HH;
        float a = bc1[h];
        #pragma unroll 8
        for (int k = 0; k < DD; ++k) a = fmaf(pooled[bb][k], Wc1[h*DD + k], a);
        h1[bb][h] = tanhf(a);
    }
    __syncthreads();
    {
        int b = tid >> 6, d = tid & 63;
        float a = bc2[d];
        #pragma unroll 8
        for (int k = 0; k < HH; ++k) a = fmaf(h1[b][k], Wc2[d*HH + k], a);
        hb[b][d] = tanhf(a);
    }
    __syncthreads();
    if (tid < DD) {
        float a = 0.5f*(hb[0][tid] + hb[1][tid]);
        agg[tid]      = a;
        comb[tid]     = g_basin[tid];
        comb[DD+tid]  = a;
    }
    __syncthreads();
    if (tid < DD) {
        float a = bu[tid];
        #pragma unroll 8
        for (int k = 0; k < 2*DD; ++k) a = fmaf(Wu[tid*2*DD + k], comb[k], a);
        float g = 1.f/(1.f + expf(-a));
        nb[tid] = g_basin[tid]*(1.f - g) + agg[tid]*g;
        g_basin[tid] = nb[tid];
    }
    __syncthreads();
    if (tid < LAYERS) {
        float acc = b_temp[tid];
        #pragma unroll 8
        for (int k = 0; k < DD; ++k) acc = fmaf(W_temp[tid*DD + k], nb[k], acc);
        g_temps[tid] = 1.f/(1.f + expf(-acc)) + 0.5f;
    }
}

// ---------------------------------------------------------------------------
extern "C" void kernel_launch(void* const* d_in, const int* in_sizes, int n_in,
                              void* d_out, int out_size) {
    const float* basin_seq    = (const float*)d_in[0];
    const float* basin_coords = (const float*)d_in[1];
    const float* W_temp       = (const float*)d_in[2];
    const float* b_temp       = (const float*)d_in[3];
    const float* res_scale    = (const float*)d_in[4];
    const float* W_fb         = (const float*)d_in[5];
    const float* b_fb         = (const float*)d_in[6];
    const float* Wc1          = (const float*)d_in[7];
    const float* bc1          = (const float*)d_in[8];
    const float* Wc2          = (const float*)d_in[9];
    const float* bc2          = (const float*)d_in[10];
    const float* Wu           = (const float*)d_in[11];
    const float* bu           = (const float*)d_in[12];
    const float* res_g        = (const float*)d_in[13];

    k_feat0<<<NTOK/8, 256>>>(basin_seq, basin_coords, W_temp, b_temp, res_scale);

    int cursel = 0;
    for (int p = 0; p < 2; ++p) {
        for (int l = 0; l < LAYERS; ++l) {
            int last = (p == 1 && l == LAYERS-1);
            int doFeat = !last;
            int nextGated = (p == 1) || (l == LAYERS-1);
            int nextL = (l + 1) & 3;
            int doPool = (p == 0 && l == LAYERS-1) ? 1 : 0;
            k_attn<<<NTOK/4, 512>>>(cursel, l, p == 0 ? 1 : 0, last, doFeat,
                                    nextGated, nextL, doPool, W_fb, b_fb,
                                    basin_seq, res_g, (float*)d_out);
            cursel ^= 1;
            if (p == 0 && l == LAYERS-1) {
                k_pool<<<1, 128>>>(Wc1, bc1, Wc2, bc2, Wu, bu, W_temp, b_temp);
            }
        }
    }
}